// round 5
// baseline (speedup 1.0000x reference)
#include <cuda_runtime.h>
#include <cuda_bf16.h>
#include <cstdint>

#define BB 64
#define SS 2048
#define DD 512
#define UU 512

// ---------------- scratch globals (no allocations allowed) ------------------
__device__ float g_bias[BB * UU];                  // dec@W2 + b1 + b2
__device__ float g_scores[BB * SS];                // pre-softmax scores
// enc converted: row r -> [hi k0..511 | lo k0..511] bf16  (256 MB)
__device__ __nv_bfloat16 g_encA[(size_t)BB * SS * 1024];
// W1 converted to [u][ hi k0..511 | lo k0..511 ]  (1 MB)
__device__ __nv_bfloat16 g_W1img[(size_t)UU * 1024];

// ---------------- helpers ----------------------------------------------------
__device__ __forceinline__ float tanh_fast(float x) {
    float e = __expf(2.0f * x);
    return 1.0f - __fdividef(2.0f, e + 1.0f);
}
__device__ __forceinline__ uint32_t smem_u32(const void* p) {
    uint32_t a;
    asm("{ .reg .u64 t; cvta.to.shared.u64 t, %1; cvt.u32.u64 %0, t; }"
        : "=r"(a) : "l"(p));
    return a;
}
__device__ __forceinline__ uint32_t pack2(__nv_bfloat16 a, __nv_bfloat16 b) {
    return ((uint32_t)__bfloat16_as_ushort(b) << 16) | __bfloat16_as_ushort(a);
}
#define CP16(dst, src) \
    asm volatile("cp.async.cg.shared.global [%0], [%1], 16;" \
                 :: "r"(dst), "l"(src) : "memory")

// ---------------------------------------------------------------------------
// kernE: enc fp32 -> bf16 hi/lo image
// ---------------------------------------------------------------------------
__global__ __launch_bounds__(256) void kernE(const float* __restrict__ enc) {
    size_t lin = (size_t)blockIdx.x * 256 + threadIdx.x;
    size_t row = lin >> 7;
    int q = (int)(lin & 127);
    float4 f = *(const float4*)(enc + row * DD + q * 4);
    __nv_bfloat16 h0 = __float2bfloat16_rn(f.x), h1 = __float2bfloat16_rn(f.y);
    __nv_bfloat16 h2 = __float2bfloat16_rn(f.z), h3 = __float2bfloat16_rn(f.w);
    __nv_bfloat16 l0 = __float2bfloat16_rn(f.x - __bfloat162float(h0));
    __nv_bfloat16 l1 = __float2bfloat16_rn(f.y - __bfloat162float(h1));
    __nv_bfloat16 l2 = __float2bfloat16_rn(f.z - __bfloat162float(h2));
    __nv_bfloat16 l3 = __float2bfloat16_rn(f.w - __bfloat162float(h3));
    uint2 hv = {pack2(h0, h1), pack2(h2, h3)};
    uint2 lv = {pack2(l0, l1), pack2(l2, l3)};
    *(uint2*)(&g_encA[row * 1024 + q * 4]) = hv;
    *(uint2*)(&g_encA[row * 1024 + 512 + q * 4]) = lv;
}

// ---------------------------------------------------------------------------
// kernW: W1[k][u] -> g_W1img[u][hi k | lo k]; also zero g_scores
// ---------------------------------------------------------------------------
__global__ __launch_bounds__(256) void kernW(const float* __restrict__ W1) {
    int idx = blockIdx.x * 256 + threadIdx.x;
    int u = idx & 511, kg = idx >> 9;
    float x = W1[(size_t)kg * UU + u];
    __nv_bfloat16 h = __float2bfloat16_rn(x);
    __nv_bfloat16 l = __float2bfloat16_rn(x - __bfloat162float(h));
    g_W1img[(size_t)u * 1024 + kg] = h;
    g_W1img[(size_t)u * 1024 + 512 + kg] = l;
    if (idx < BB * SS) g_scores[idx] = 0.0f;
}

// ---------------------------------------------------------------------------
// kernA: g_bias[b,u] = dec@W2 + b1 + b2
// ---------------------------------------------------------------------------
__global__ __launch_bounds__(512) void kernA(const float* __restrict__ dec,
                                             const float* __restrict__ W2,
                                             const float* __restrict__ b1,
                                             const float* __restrict__ b2) {
    __shared__ float ds[DD];
    int b = blockIdx.x;
    for (int i = threadIdx.x; i < DD; i += blockDim.x) ds[i] = dec[b * DD + i];
    __syncthreads();
    int u = threadIdx.x;
    float acc = 0.0f;
#pragma unroll 8
    for (int k = 0; k < DD; k++) acc = fmaf(ds[k], W2[k * UU + u], acc);
    g_bias[b * UU + u] = acc + b1[u] + b2[u];
}

// ---------------------------------------------------------------------------
// kernB: bf16 mma.sync GEMM, tile M128 x N128 per CTA, K'=1536 (3 passes).
// 3-stage cp.async ring, one __syncthreads per k-tile, 2 CTAs/SM.
// ---------------------------------------------------------------------------
#define ASLOT 18432             // 128 rows * 144 B
#define SLOT  36864             // A + B per stage
#define EXTRA 110592            // 3 stages
#define SMEM_B_TOTAL (EXTRA + 512 + 512 + 2048)

__global__ __launch_bounds__(256, 2) void kernB(const float* __restrict__ Vp) {
    extern __shared__ char smraw[];
    const uint32_t smem = smem_u32(smraw);
    float* gBs = (float*)(smraw + EXTRA);
    float* Vs = (float*)(smraw + EXTRA + 512);
    float* sPart = (float*)(smraw + EXTRA + 1024);

    const int tid = threadIdx.x;
    const int lane = tid & 31, w = tid >> 5;
    const int wm = w & 1, wn = w >> 1;          // wn 0..3
    const int R = blockIdx.x * 128;
    const int b = blockIdx.x >> 4;
    const int s0 = (blockIdx.x & 15) * 128;
    const int N0 = blockIdx.y * 128;

    if (tid < 128) {
        gBs[tid] = g_bias[b * 512 + N0 + tid];
        Vs[tid] = Vp[N0 + tid];
    }

    // tile it: pass p = it/8 (0: hi*hi, 1: hi*lo, 2: lo*hi), k0 = (it%8)*64
    auto issue_tile = [&](int it, int slot) {
        int p = it >> 3;
        int k0 = (it & 7) * 64;
        uint32_t aPart = (p < 2) ? 0u : 1024u;
        uint32_t bPart = (p == 1) ? 1024u : 0u;
        const char* aSrc = (const char*)g_encA + (size_t)R * 2048 + aPart + k0 * 2;
        const char* bSrc = (const char*)g_W1img + (size_t)N0 * 2048 + bPart + k0 * 2;
        uint32_t aDst = smem + slot * SLOT;
        uint32_t bDst = aDst + ASLOT;
        int row = tid >> 1;                 // 2 chunks per row per thread pair
        int c2 = (tid & 1) * 4;             // chunks 0-3 or 4-7
        CP16(aDst + row * 144 + c2 * 16,        aSrc + (size_t)row * 2048 + c2 * 16);
        CP16(aDst + row * 144 + (c2 + 1) * 16,  aSrc + (size_t)row * 2048 + (c2 + 1) * 16);
        CP16(aDst + row * 144 + (c2 + 2) * 16,  aSrc + (size_t)row * 2048 + (c2 + 2) * 16);
        CP16(aDst + row * 144 + (c2 + 3) * 16,  aSrc + (size_t)row * 2048 + (c2 + 3) * 16);
        CP16(bDst + row * 144 + c2 * 16,        bSrc + (size_t)row * 2048 + c2 * 16);
        CP16(bDst + row * 144 + (c2 + 1) * 16,  bSrc + (size_t)row * 2048 + (c2 + 1) * 16);
        CP16(bDst + row * 144 + (c2 + 2) * 16,  bSrc + (size_t)row * 2048 + (c2 + 2) * 16);
        CP16(bDst + row * 144 + (c2 + 3) * 16,  bSrc + (size_t)row * 2048 + (c2 + 3) * 16);
        asm volatile("cp.async.commit_group;" ::: "memory");
    };

    float acc[4][4][4];
#pragma unroll
    for (int mt = 0; mt < 4; mt++)
#pragma unroll
        for (int nt = 0; nt < 4; nt++)
#pragma unroll
            for (int j = 0; j < 4; j++) acc[mt][nt][j] = 0.0f;

    issue_tile(0, 0);
    issue_tile(1, 1);

    const uint32_t aRowOff =
        (uint32_t)((wm * 64 + (lane & 15)) * 144 + ((lane >> 4) & 1) * 16);
    // B x4: row = wn*32 + (lane&7) + bit4*8 ; col16 = bit3
    const uint32_t bRowOff =
        (uint32_t)((wn * 32 + (lane & 7) + ((lane >> 4) & 1) * 8) * 144 +
                   ((lane >> 3) & 1) * 16);

    for (int it = 0; it < 24; it++) {
        if (it < 23)
            asm volatile("cp.async.wait_group 1;" ::: "memory");
        else
            asm volatile("cp.async.wait_group 0;" ::: "memory");
        __syncthreads();
        if (it + 2 < 24) issue_tile(it + 2, (it + 2) % 3);

        const uint32_t sbase = smem + (it % 3) * SLOT;
        const uint32_t sA = sbase + aRowOff;
        const uint32_t sB = sbase + ASLOT + bRowOff;
#pragma unroll
        for (int ks = 0; ks < 4; ks++) {
            uint32_t a[4][4];
#pragma unroll
            for (int mt = 0; mt < 4; mt++) {
                asm volatile(
                    "ldmatrix.sync.aligned.m8n8.x4.shared.b16 {%0,%1,%2,%3}, [%4];"
                    : "=r"(a[mt][0]), "=r"(a[mt][1]), "=r"(a[mt][2]), "=r"(a[mt][3])
                    : "r"(sA + mt * 16 * 144 + ks * 32));
            }
            uint32_t bf[4][2];
#pragma unroll
            for (int ntp = 0; ntp < 2; ntp++) {
                asm volatile(
                    "ldmatrix.sync.aligned.m8n8.x4.shared.b16 {%0,%1,%2,%3}, [%4];"
                    : "=r"(bf[ntp * 2][0]), "=r"(bf[ntp * 2][1]),
                      "=r"(bf[ntp * 2 + 1][0]), "=r"(bf[ntp * 2 + 1][1])
                    : "r"(sB + ntp * 16 * 144 + ks * 32));
            }
#pragma unroll
            for (int mt = 0; mt < 4; mt++)
#pragma unroll
                for (int nt = 0; nt < 4; nt++) {
                    asm volatile(
                        "mma.sync.aligned.m16n8k16.row.col.f32.bf16.bf16.f32 "
                        "{%0,%1,%2,%3}, {%4,%5,%6,%7}, {%8,%9}, {%0,%1,%2,%3};"
                        : "+f"(acc[mt][nt][0]), "+f"(acc[mt][nt][1]),
                          "+f"(acc[mt][nt][2]), "+f"(acc[mt][nt][3])
                        : "r"(a[mt][0]), "r"(a[mt][1]), "r"(a[mt][2]), "r"(a[mt][3]),
                          "r"(bf[nt][0]), "r"(bf[nt][1]));
                }
        }
    }

    // ---- epilogue: bias + tanh + V-dot ----
    __syncthreads();
    const int t4 = lane & 3;
    float part[4][2];
#pragma unroll
    for (int mt = 0; mt < 4; mt++) { part[mt][0] = 0.f; part[mt][1] = 0.f; }
#pragma unroll
    for (int mt = 0; mt < 4; mt++)
#pragma unroll
        for (int nt = 0; nt < 4; nt++) {
            int n0 = wn * 32 + nt * 8 + 2 * t4;
            float v0 = Vs[n0], v1 = Vs[n0 + 1];
            float g0 = gBs[n0], g1 = gBs[n0 + 1];
            part[mt][0] += tanh_fast(acc[mt][nt][0] + g0) * v0 +
                           tanh_fast(acc[mt][nt][1] + g1) * v1;
            part[mt][1] += tanh_fast(acc[mt][nt][2] + g0) * v0 +
                           tanh_fast(acc[mt][nt][3] + g1) * v1;
        }
#pragma unroll
    for (int mt = 0; mt < 4; mt++)
#pragma unroll
        for (int rr = 0; rr < 2; rr++) {
            part[mt][rr] += __shfl_xor_sync(0xffffffffu, part[mt][rr], 1);
            part[mt][rr] += __shfl_xor_sync(0xffffffffu, part[mt][rr], 2);
        }
    if (t4 == 0) {
        int g = lane >> 2;
#pragma unroll
        for (int mt = 0; mt < 4; mt++)
#pragma unroll
            for (int rr = 0; rr < 2; rr++) {
                int row = wm * 64 + mt * 16 + rr * 8 + g;
                sPart[row * 4 + wn] = part[mt][rr];
            }
    }
    __syncthreads();
    if (tid < 128) {
        float s = sPart[tid * 4] + sPart[tid * 4 + 1] + sPart[tid * 4 + 2] +
                  sPart[tid * 4 + 3];
        atomicAdd(&g_scores[b * SS + s0 + tid], s);
    }
}

// ---------------------------------------------------------------------------
// kernC: softmax over S; writes attn; zeroes context region
// ---------------------------------------------------------------------------
__global__ __launch_bounds__(256) void kernC(float* __restrict__ out) {
    __shared__ float red[256];
    int b = blockIdx.x, tid = threadIdx.x;
    float v[8];
    float mx = -1e30f;
#pragma unroll
    for (int j = 0; j < 8; j++) {
        v[j] = g_scores[b * SS + tid + j * 256];
        mx = fmaxf(mx, v[j]);
    }
    red[tid] = mx;
    __syncthreads();
    for (int o = 128; o > 0; o >>= 1) {
        if (tid < o) red[tid] = fmaxf(red[tid], red[tid + o]);
        __syncthreads();
    }
    mx = red[0];
    __syncthreads();
    float s = 0.0f;
#pragma unroll
    for (int j = 0; j < 8; j++) {
        v[j] = __expf(v[j] - mx);
        s += v[j];
    }
    red[tid] = s;
    __syncthreads();
    for (int o = 128; o > 0; o >>= 1) {
        if (tid < o) red[tid] += red[tid + o];
        __syncthreads();
    }
    float inv = 1.0f / red[0];
#pragma unroll
    for (int j = 0; j < 8; j++)
        out[BB * UU + b * SS + tid + j * 256] = v[j] * inv;
    for (int i = tid; i < 512; i += 256) out[b * 512 + i] = 0.0f;
}

// ---------------------------------------------------------------------------
// kernD: context[b,d] = sum_s attn[b,s] * enc[b,s,d]
// ---------------------------------------------------------------------------
__global__ __launch_bounds__(512) void kernD(const float* __restrict__ enc,
                                             float* __restrict__ out) {
    __shared__ float as[128];
    int b = blockIdx.y, c = blockIdx.x, tid = threadIdx.x;
    if (tid < 128) as[tid] = out[BB * UU + b * SS + c * 128 + tid];
    __syncthreads();
    const float* e = enc + ((size_t)(b * SS + c * 128)) * DD + tid;
    float acc = 0.0f;
#pragma unroll 8
    for (int i = 0; i < 128; i++) acc = fmaf(as[i], e[(size_t)i * DD], acc);
    atomicAdd(&out[b * 512 + tid], acc);
}

// ---------------------------------------------------------------------------
extern "C" void kernel_launch(void* const* d_in, const int* in_sizes, int n_in,
                              void* d_out, int out_size) {
    const float* enc = (const float*)d_in[0];
    const float* dec = (const float*)d_in[1];
    const float* W1  = (const float*)d_in[2];
    const float* b1  = (const float*)d_in[3];
    const float* W2  = (const float*)d_in[4];
    const float* b2  = (const float*)d_in[5];
    const float* V   = (const float*)d_in[6];
    float* out = (float*)d_out;

    cudaFuncSetAttribute(kernB, cudaFuncAttributeMaxDynamicSharedMemorySize,
                         SMEM_B_TOTAL);

    kernE<<<65536, 256>>>(enc);
    kernW<<<1024, 256>>>(W1);
    kernA<<<BB, 512>>>(dec, W2, b1, b2);
    kernB<<<dim3(1024, 4), 256, SMEM_B_TOTAL>>>(V);
    kernC<<<BB, 256>>>(out);
    kernD<<<dim3(16, BB), 512>>>(enc, out);
}

// round 6
// speedup vs baseline: 1.2493x; 1.2493x over previous
#include <cuda_runtime.h>
#include <cuda_bf16.h>
#include <cstdint>

#define BB 64
#define SS 2048
#define DD 512
#define UU 512

// ---------------- scratch globals (no allocations allowed) ------------------
__device__ float g_bias[BB * UU];                  // dec@W2 + b1 + b2
__device__ float g_scores[BB * SS];                // pre-softmax scores
// enc converted: row r -> [hi k0..511 | lo k0..511] bf16  (256 MB)
__device__ __nv_bfloat16 g_encA[(size_t)BB * SS * 1024];
// W1 converted to [u][ hi k0..511 | lo k0..511 ]  (1 MB)
__device__ __nv_bfloat16 g_W1img[(size_t)UU * 1024];

// ---------------- helpers ----------------------------------------------------
__device__ __forceinline__ float tanh_fast(float x) {
    float e = __expf(2.0f * x);
    return 1.0f - __fdividef(2.0f, e + 1.0f);
}
__device__ __forceinline__ uint32_t smem_u32(const void* p) {
    uint32_t a;
    asm("{ .reg .u64 t; cvta.to.shared.u64 t, %1; cvt.u32.u64 %0, t; }"
        : "=r"(a) : "l"(p));
    return a;
}
__device__ __forceinline__ uint32_t pack2(__nv_bfloat16 a, __nv_bfloat16 b) {
    return ((uint32_t)__bfloat16_as_ushort(b) << 16) | __bfloat16_as_ushort(a);
}
#define CP16(dst, src) \
    asm volatile("cp.async.cg.shared.global [%0], [%1], 16;" \
                 :: "r"(dst), "l"(src) : "memory")

// ---------------------------------------------------------------------------
// kernE: enc fp32 -> bf16 hi/lo image
// ---------------------------------------------------------------------------
__global__ __launch_bounds__(256) void kernE(const float* __restrict__ enc) {
    size_t lin = (size_t)blockIdx.x * 256 + threadIdx.x;
    size_t row = lin >> 7;
    int q = (int)(lin & 127);
    float4 f = *(const float4*)(enc + row * DD + q * 4);
    __nv_bfloat16 h0 = __float2bfloat16_rn(f.x), h1 = __float2bfloat16_rn(f.y);
    __nv_bfloat16 h2 = __float2bfloat16_rn(f.z), h3 = __float2bfloat16_rn(f.w);
    __nv_bfloat16 l0 = __float2bfloat16_rn(f.x - __bfloat162float(h0));
    __nv_bfloat16 l1 = __float2bfloat16_rn(f.y - __bfloat162float(h1));
    __nv_bfloat16 l2 = __float2bfloat16_rn(f.z - __bfloat162float(h2));
    __nv_bfloat16 l3 = __float2bfloat16_rn(f.w - __bfloat162float(h3));
    uint2 hv = {pack2(h0, h1), pack2(h2, h3)};
    uint2 lv = {pack2(l0, l1), pack2(l2, l3)};
    *(uint2*)(&g_encA[row * 1024 + q * 4]) = hv;
    *(uint2*)(&g_encA[row * 1024 + 512 + q * 4]) = lv;
}

// ---------------------------------------------------------------------------
// kernW: W1[k][u] -> g_W1img[u][hi k | lo k]; also zero g_scores
// ---------------------------------------------------------------------------
__global__ __launch_bounds__(256) void kernW(const float* __restrict__ W1) {
    int idx = blockIdx.x * 256 + threadIdx.x;
    int u = idx & 511, kg = idx >> 9;
    float x = W1[(size_t)kg * UU + u];
    __nv_bfloat16 h = __float2bfloat16_rn(x);
    __nv_bfloat16 l = __float2bfloat16_rn(x - __bfloat162float(h));
    g_W1img[(size_t)u * 1024 + kg] = h;
    g_W1img[(size_t)u * 1024 + 512 + kg] = l;
    if (idx < BB * SS) g_scores[idx] = 0.0f;
}

// ---------------------------------------------------------------------------
// kernA: g_bias[b,u] = dec@W2 + b1 + b2
// ---------------------------------------------------------------------------
__global__ __launch_bounds__(512) void kernA(const float* __restrict__ dec,
                                             const float* __restrict__ W2,
                                             const float* __restrict__ b1,
                                             const float* __restrict__ b2) {
    __shared__ float ds[DD];
    int b = blockIdx.x;
    for (int i = threadIdx.x; i < DD; i += blockDim.x) ds[i] = dec[b * DD + i];
    __syncthreads();
    int u = threadIdx.x;
    float acc = 0.0f;
#pragma unroll 8
    for (int k = 0; k < DD; k++) acc = fmaf(ds[k], W2[k * UU + u], acc);
    g_bias[b * UU + u] = acc + b1[u] + b2[u];
}

// ---------------------------------------------------------------------------
// kernB: bf16 mma.sync GEMM, tile M128 x N256 per CTA, K'=1536 (3 passes).
// 3-stage cp.async ring, ONE __syncthreads per k-tile, prefetch distance 2.
// ---------------------------------------------------------------------------
#define ASLOT 18432             // 128 rows * 144 B
#define SLOT  55296             // A (18432) + B (36864) per stage
#define EXTRA 165888            // 3 stages
#define SMEM_B_TOTAL (EXTRA + 1024 + 1024 + 2048)

__global__ __launch_bounds__(256, 1) void kernB(const float* __restrict__ Vp) {
    extern __shared__ char smraw[];
    const uint32_t smem = smem_u32(smraw);
    float* gBs = (float*)(smraw + EXTRA);
    float* Vs = (float*)(smraw + EXTRA + 1024);
    float* sPart = (float*)(smraw + EXTRA + 2048);

    const int tid = threadIdx.x;
    const int lane = tid & 31, w = tid >> 5;
    const int wm = w & 1, wn = w >> 1;          // wn 0..3, warp tile 64x64
    const int R = blockIdx.x * 128;
    const int b = blockIdx.x >> 4;
    const int s0 = (blockIdx.x & 15) * 128;
    const int N0 = blockIdx.y * 256;

    for (int i = tid; i < 256; i += 256) {
        gBs[i] = g_bias[b * 512 + N0 + i];
        Vs[i] = Vp[N0 + i];
    }

    // tile it: pass p = it/8 (0: hi*hi, 1: hi*lo, 2: lo*hi), k0 = (it%8)*64
    auto issue_tile = [&](int it, int slot) {
        int p = it >> 3;
        int k0 = (it & 7) * 64;
        uint32_t aPart = (p < 2) ? 0u : 1024u;
        uint32_t bPart = (p == 1) ? 1024u : 0u;
        const char* aSrc = (const char*)g_encA + (size_t)R * 2048 + aPart + k0 * 2;
        const char* bSrc = (const char*)g_W1img + (size_t)N0 * 2048 + bPart + k0 * 2;
        uint32_t aDst = smem + slot * SLOT;
        uint32_t bDst = aDst + ASLOT;
#pragma unroll
        for (int i = 0; i < 4; i++) {
            int lin = tid + i * 256;
            int row = lin >> 3, c = lin & 7;
            CP16(aDst + row * 144 + c * 16, aSrc + (size_t)row * 2048 + c * 16);
        }
#pragma unroll
        for (int i = 0; i < 8; i++) {
            int lin = tid + i * 256;
            int row = lin >> 3, c = lin & 7;
            CP16(bDst + row * 144 + c * 16, bSrc + (size_t)row * 2048 + c * 16);
        }
        asm volatile("cp.async.commit_group;" ::: "memory");
    };

    float acc[4][8][4];
#pragma unroll
    for (int mt = 0; mt < 4; mt++)
#pragma unroll
        for (int nt = 0; nt < 8; nt++)
#pragma unroll
            for (int j = 0; j < 4; j++) acc[mt][nt][j] = 0.0f;

    issue_tile(0, 0);
    issue_tile(1, 1);

    const uint32_t aRowOff =
        (uint32_t)((wm * 64 + (lane & 15)) * 144 + ((lane >> 4) & 1) * 16);
    // B x4 (two 8-row n-tiles per load): row = wn*64 + (lane&7) + bit4*8
    const uint32_t bRowOff =
        (uint32_t)((wn * 64 + (lane & 7) + ((lane >> 4) & 1) * 8) * 144 +
                   ((lane >> 3) & 1) * 16);

    for (int it = 0; it < 24; it++) {
        if (it < 23)
            asm volatile("cp.async.wait_group 1;" ::: "memory");
        else
            asm volatile("cp.async.wait_group 0;" ::: "memory");
        __syncthreads();
        if (it + 2 < 24) issue_tile(it + 2, (it + 2) % 3);

        const uint32_t sbase = smem + (it % 3) * SLOT;
        const uint32_t sA = sbase + aRowOff;
        const uint32_t sB = sbase + ASLOT + bRowOff;
#pragma unroll
        for (int ks = 0; ks < 4; ks++) {
            uint32_t a[4][4];
#pragma unroll
            for (int mt = 0; mt < 4; mt++) {
                asm volatile(
                    "ldmatrix.sync.aligned.m8n8.x4.shared.b16 {%0,%1,%2,%3}, [%4];"
                    : "=r"(a[mt][0]), "=r"(a[mt][1]), "=r"(a[mt][2]), "=r"(a[mt][3])
                    : "r"(sA + mt * 16 * 144 + ks * 32));
            }
            uint32_t bq[8][2];
#pragma unroll
            for (int ntp = 0; ntp < 4; ntp++) {
                asm volatile(
                    "ldmatrix.sync.aligned.m8n8.x4.shared.b16 {%0,%1,%2,%3}, [%4];"
                    : "=r"(bq[ntp * 2][0]), "=r"(bq[ntp * 2][1]),
                      "=r"(bq[ntp * 2 + 1][0]), "=r"(bq[ntp * 2 + 1][1])
                    : "r"(sB + ntp * 16 * 144 + ks * 32));
            }
#pragma unroll
            for (int mt = 0; mt < 4; mt++)
#pragma unroll
                for (int nt = 0; nt < 8; nt++) {
                    asm volatile(
                        "mma.sync.aligned.m16n8k16.row.col.f32.bf16.bf16.f32 "
                        "{%0,%1,%2,%3}, {%4,%5,%6,%7}, {%8,%9}, {%0,%1,%2,%3};"
                        : "+f"(acc[mt][nt][0]), "+f"(acc[mt][nt][1]),
                          "+f"(acc[mt][nt][2]), "+f"(acc[mt][nt][3])
                        : "r"(a[mt][0]), "r"(a[mt][1]), "r"(a[mt][2]), "r"(a[mt][3]),
                          "r"(bq[nt][0]), "r"(bq[nt][1]));
                }
        }
    }

    // ---- epilogue: bias + tanh + V-dot, reduce to per-row partials ----
    __syncthreads();
    const int t4 = lane & 3;
    float part[4][2];
#pragma unroll
    for (int mt = 0; mt < 4; mt++) { part[mt][0] = 0.f; part[mt][1] = 0.f; }
#pragma unroll
    for (int mt = 0; mt < 4; mt++)
#pragma unroll
        for (int nt = 0; nt < 8; nt++) {
            int n0 = wn * 64 + nt * 8 + 2 * t4;
            float v0 = Vs[n0], v1 = Vs[n0 + 1];
            float g0 = gBs[n0], g1 = gBs[n0 + 1];
            part[mt][0] += tanh_fast(acc[mt][nt][0] + g0) * v0 +
                           tanh_fast(acc[mt][nt][1] + g1) * v1;
            part[mt][1] += tanh_fast(acc[mt][nt][2] + g0) * v0 +
                           tanh_fast(acc[mt][nt][3] + g1) * v1;
        }
#pragma unroll
    for (int mt = 0; mt < 4; mt++)
#pragma unroll
        for (int rr = 0; rr < 2; rr++) {
            part[mt][rr] += __shfl_xor_sync(0xffffffffu, part[mt][rr], 1);
            part[mt][rr] += __shfl_xor_sync(0xffffffffu, part[mt][rr], 2);
        }
    if (t4 == 0) {
        int g = lane >> 2;
#pragma unroll
        for (int mt = 0; mt < 4; mt++)
#pragma unroll
            for (int rr = 0; rr < 2; rr++) {
                int row = wm * 64 + mt * 16 + rr * 8 + g;
                sPart[row * 4 + wn] = part[mt][rr];
            }
    }
    __syncthreads();
    if (tid < 128) {
        float s = sPart[tid * 4] + sPart[tid * 4 + 1] + sPart[tid * 4 + 2] +
                  sPart[tid * 4 + 3];
        atomicAdd(&g_scores[b * SS + s0 + tid], s);
    }
}

// ---------------------------------------------------------------------------
// kernC: softmax over S; writes attn; zeroes context region
// ---------------------------------------------------------------------------
__global__ __launch_bounds__(256) void kernC(float* __restrict__ out) {
    __shared__ float red[256];
    int b = blockIdx.x, tid = threadIdx.x;
    float v[8];
    float mx = -1e30f;
#pragma unroll
    for (int j = 0; j < 8; j++) {
        v[j] = g_scores[b * SS + tid + j * 256];
        mx = fmaxf(mx, v[j]);
    }
    red[tid] = mx;
    __syncthreads();
    for (int o = 128; o > 0; o >>= 1) {
        if (tid < o) red[tid] = fmaxf(red[tid], red[tid + o]);
        __syncthreads();
    }
    mx = red[0];
    __syncthreads();
    float s = 0.0f;
#pragma unroll
    for (int j = 0; j < 8; j++) {
        v[j] = __expf(v[j] - mx);
        s += v[j];
    }
    red[tid] = s;
    __syncthreads();
    for (int o = 128; o > 0; o >>= 1) {
        if (tid < o) red[tid] += red[tid + o];
        __syncthreads();
    }
    float inv = 1.0f / red[0];
#pragma unroll
    for (int j = 0; j < 8; j++)
        out[BB * UU + b * SS + tid + j * 256] = v[j] * inv;
    for (int i = tid; i < 512; i += 256) out[b * 512 + i] = 0.0f;
}

// ---------------------------------------------------------------------------
// kernD: context[b,d] = sum_s attn[b,s] * enc[b,s,d]
// ---------------------------------------------------------------------------
__global__ __launch_bounds__(512) void kernD(const float* __restrict__ enc,
                                             float* __restrict__ out) {
    __shared__ float as[128];
    int b = blockIdx.y, c = blockIdx.x, tid = threadIdx.x;
    if (tid < 128) as[tid] = out[BB * UU + b * SS + c * 128 + tid];
    __syncthreads();
    const float* e = enc + ((size_t)(b * SS + c * 128)) * DD + tid;
    float acc = 0.0f;
#pragma unroll 8
    for (int i = 0; i < 128; i++) acc = fmaf(as[i], e[(size_t)i * DD], acc);
    atomicAdd(&out[b * 512 + tid], acc);
}

// ---------------------------------------------------------------------------
extern "C" void kernel_launch(void* const* d_in, const int* in_sizes, int n_in,
                              void* d_out, int out_size) {
    const float* enc = (const float*)d_in[0];
    const float* dec = (const float*)d_in[1];
    const float* W1  = (const float*)d_in[2];
    const float* b1  = (const float*)d_in[3];
    const float* W2  = (const float*)d_in[4];
    const float* b2  = (const float*)d_in[5];
    const float* V   = (const float*)d_in[6];
    float* out = (float*)d_out;

    cudaFuncSetAttribute(kernB, cudaFuncAttributeMaxDynamicSharedMemorySize,
                         SMEM_B_TOTAL);

    kernE<<<65536, 256>>>(enc);
    kernW<<<1024, 256>>>(W1);
    kernA<<<BB, 512>>>(dec, W2, b1, b2);
    kernB<<<dim3(1024, 2), 256, SMEM_B_TOTAL>>>(V);
    kernC<<<BB, 256>>>(out);
    kernD<<<dim3(16, BB), 512>>>(enc, out);
}

// round 7
// speedup vs baseline: 1.2617x; 1.0099x over previous
#include <cuda_runtime.h>
#include <cuda_bf16.h>
#include <cstdint>

#define BB 64
#define SS 2048
#define DD 512
#define UU 512

// ---------------- scratch globals (no allocations allowed) ------------------
__device__ float g_bias[BB * UU];                  // dec@W2 + b1 + b2
__device__ float g_scores[BB * SS];                // pre-softmax scores
// enc converted: row r -> [hi k0..511 | lo k0..511] bf16  (256 MB)
__device__ __nv_bfloat16 g_encA[(size_t)BB * SS * 1024];
// W1 converted to [u][ hi k0..511 | lo k0..511 ]  (1 MB)
__device__ __nv_bfloat16 g_W1img[(size_t)UU * 1024];

// ---------------- helpers ----------------------------------------------------
__device__ __forceinline__ float tanh_fast(float x) {
    float e = __expf(2.0f * x);
    return 1.0f - __fdividef(2.0f, e + 1.0f);
}
__device__ __forceinline__ uint32_t smem_u32(const void* p) {
    uint32_t a;
    asm("{ .reg .u64 t; cvta.to.shared.u64 t, %1; cvt.u32.u64 %0, t; }"
        : "=r"(a) : "l"(p));
    return a;
}
__device__ __forceinline__ uint32_t pack2(__nv_bfloat16 a, __nv_bfloat16 b) {
    return ((uint32_t)__bfloat16_as_ushort(b) << 16) | __bfloat16_as_ushort(a);
}
#define CP16(dst, src) \
    asm volatile("cp.async.cg.shared.global [%0], [%1], 16;" \
                 :: "r"(dst), "l"(src) : "memory")

// ---------------------------------------------------------------------------
// kernE: enc fp32 -> bf16 hi/lo image
// ---------------------------------------------------------------------------
__global__ __launch_bounds__(256) void kernE(const float* __restrict__ enc) {
    size_t lin = (size_t)blockIdx.x * 256 + threadIdx.x;
    size_t row = lin >> 7;
    int q = (int)(lin & 127);
    float4 f = *(const float4*)(enc + row * DD + q * 4);
    __nv_bfloat16 h0 = __float2bfloat16_rn(f.x), h1 = __float2bfloat16_rn(f.y);
    __nv_bfloat16 h2 = __float2bfloat16_rn(f.z), h3 = __float2bfloat16_rn(f.w);
    __nv_bfloat16 l0 = __float2bfloat16_rn(f.x - __bfloat162float(h0));
    __nv_bfloat16 l1 = __float2bfloat16_rn(f.y - __bfloat162float(h1));
    __nv_bfloat16 l2 = __float2bfloat16_rn(f.z - __bfloat162float(h2));
    __nv_bfloat16 l3 = __float2bfloat16_rn(f.w - __bfloat162float(h3));
    uint2 hv = {pack2(h0, h1), pack2(h2, h3)};
    uint2 lv = {pack2(l0, l1), pack2(l2, l3)};
    *(uint2*)(&g_encA[row * 1024 + q * 4]) = hv;
    *(uint2*)(&g_encA[row * 1024 + 512 + q * 4]) = lv;
}

// ---------------------------------------------------------------------------
// kernW: W1[k][u] -> g_W1img[u][hi k | lo k]; also zero g_scores
// ---------------------------------------------------------------------------
__global__ __launch_bounds__(256) void kernW(const float* __restrict__ W1) {
    int idx = blockIdx.x * 256 + threadIdx.x;
    int u = idx & 511, kg = idx >> 9;
    float x = W1[(size_t)kg * UU + u];
    __nv_bfloat16 h = __float2bfloat16_rn(x);
    __nv_bfloat16 l = __float2bfloat16_rn(x - __bfloat162float(h));
    g_W1img[(size_t)u * 1024 + kg] = h;
    g_W1img[(size_t)u * 1024 + 512 + kg] = l;
    if (idx < BB * SS) g_scores[idx] = 0.0f;
}

// ---------------------------------------------------------------------------
// kernA: g_bias[b,u] = dec@W2 + b1 + b2
// ---------------------------------------------------------------------------
__global__ __launch_bounds__(512) void kernA(const float* __restrict__ dec,
                                             const float* __restrict__ W2,
                                             const float* __restrict__ b1,
                                             const float* __restrict__ b2) {
    __shared__ float ds[DD];
    int b = blockIdx.x;
    for (int i = threadIdx.x; i < DD; i += blockDim.x) ds[i] = dec[b * DD + i];
    __syncthreads();
    int u = threadIdx.x;
    float acc = 0.0f;
#pragma unroll 8
    for (int k = 0; k < DD; k++) acc = fmaf(ds[k], W2[k * UU + u], acc);
    g_bias[b * UU + u] = acc + b1[u] + b2[u];
}

// ---------------------------------------------------------------------------
// kernB: bf16 mma.sync GEMM, tile M128 x N256 per CTA, K'=1536 (3 passes).
// 512 threads (16 warps), warp tile 32x64, 3-stage cp.async ring,
// one __syncthreads per k-tile, prefetch distance 2, regs capped at 128.
// ---------------------------------------------------------------------------
#define ASLOT 18432             // 128 rows * 144 B
#define SLOT  55296             // A (18432) + B (36864) per stage
#define EXTRA 165888            // 3 stages
#define SMEM_B_TOTAL (EXTRA + 1024 + 1024 + 2048)

__global__ __launch_bounds__(512, 1) void kernB(const float* __restrict__ Vp) {
    extern __shared__ char smraw[];
    const uint32_t smem = smem_u32(smraw);
    float* gBs = (float*)(smraw + EXTRA);
    float* Vs = (float*)(smraw + EXTRA + 1024);
    float* sPart = (float*)(smraw + EXTRA + 2048);

    const int tid = threadIdx.x;
    const int lane = tid & 31, w = tid >> 5;
    const int wm = w & 3, wn = w >> 2;          // warp tile 32(M) x 64(N)
    const int R = blockIdx.x * 128;
    const int b = blockIdx.x >> 4;
    const int s0 = (blockIdx.x & 15) * 128;
    const int N0 = blockIdx.y * 256;

    if (tid < 256) {
        gBs[tid] = g_bias[b * 512 + N0 + tid];
        Vs[tid] = Vp[N0 + tid];
    }

    // tile it: pass p = it/8 (0: hi*hi, 1: hi*lo, 2: lo*hi), k0 = (it%8)*64
    auto issue_tile = [&](int it, int slot) {
        int p = it >> 3;
        int k0 = (it & 7) * 64;
        uint32_t aPart = (p < 2) ? 0u : 1024u;
        uint32_t bPart = (p == 1) ? 1024u : 0u;
        const char* aSrc = (const char*)g_encA + (size_t)R * 2048 + aPart + k0 * 2;
        const char* bSrc = (const char*)g_W1img + (size_t)N0 * 2048 + bPart + k0 * 2;
        uint32_t aDst = smem + slot * SLOT;
        uint32_t bDst = aDst + ASLOT;
#pragma unroll
        for (int i = 0; i < 2; i++) {
            int lin = tid + i * 512;
            int row = lin >> 3, c = lin & 7;
            CP16(aDst + row * 144 + c * 16, aSrc + (size_t)row * 2048 + c * 16);
        }
#pragma unroll
        for (int i = 0; i < 4; i++) {
            int lin = tid + i * 512;
            int row = lin >> 3, c = lin & 7;
            CP16(bDst + row * 144 + c * 16, bSrc + (size_t)row * 2048 + c * 16);
        }
        asm volatile("cp.async.commit_group;" ::: "memory");
    };

    float acc[2][8][4];
#pragma unroll
    for (int mt = 0; mt < 2; mt++)
#pragma unroll
        for (int nt = 0; nt < 8; nt++)
#pragma unroll
            for (int j = 0; j < 4; j++) acc[mt][nt][j] = 0.0f;

    issue_tile(0, 0);
    issue_tile(1, 1);

    const uint32_t aRowOff =
        (uint32_t)((wm * 32 + (lane & 15)) * 144 + ((lane >> 4) & 1) * 16);
    // B x4 (two 8-row n-tiles per load): row = wn*64 + (lane&7) + bit4*8
    const uint32_t bRowOff =
        (uint32_t)((wn * 64 + (lane & 7) + ((lane >> 4) & 1) * 8) * 144 +
                   ((lane >> 3) & 1) * 16);

    for (int it = 0; it < 24; it++) {
        if (it < 23)
            asm volatile("cp.async.wait_group 1;" ::: "memory");
        else
            asm volatile("cp.async.wait_group 0;" ::: "memory");
        __syncthreads();
        if (it + 2 < 24) issue_tile(it + 2, (it + 2) % 3);

        const uint32_t sbase = smem + (it % 3) * SLOT;
        const uint32_t sA = sbase + aRowOff;
        const uint32_t sB = sbase + ASLOT + bRowOff;
#pragma unroll
        for (int ks = 0; ks < 4; ks++) {
            uint32_t a[2][4];
#pragma unroll
            for (int mt = 0; mt < 2; mt++) {
                asm volatile(
                    "ldmatrix.sync.aligned.m8n8.x4.shared.b16 {%0,%1,%2,%3}, [%4];"
                    : "=r"(a[mt][0]), "=r"(a[mt][1]), "=r"(a[mt][2]), "=r"(a[mt][3])
                    : "r"(sA + mt * 16 * 144 + ks * 32));
            }
            uint32_t bq[8][2];
#pragma unroll
            for (int ntp = 0; ntp < 4; ntp++) {
                asm volatile(
                    "ldmatrix.sync.aligned.m8n8.x4.shared.b16 {%0,%1,%2,%3}, [%4];"
                    : "=r"(bq[ntp * 2][0]), "=r"(bq[ntp * 2][1]),
                      "=r"(bq[ntp * 2 + 1][0]), "=r"(bq[ntp * 2 + 1][1])
                    : "r"(sB + ntp * 16 * 144 + ks * 32));
            }
#pragma unroll
            for (int mt = 0; mt < 2; mt++)
#pragma unroll
                for (int nt = 0; nt < 8; nt++) {
                    asm volatile(
                        "mma.sync.aligned.m16n8k16.row.col.f32.bf16.bf16.f32 "
                        "{%0,%1,%2,%3}, {%4,%5,%6,%7}, {%8,%9}, {%0,%1,%2,%3};"
                        : "+f"(acc[mt][nt][0]), "+f"(acc[mt][nt][1]),
                          "+f"(acc[mt][nt][2]), "+f"(acc[mt][nt][3])
                        : "r"(a[mt][0]), "r"(a[mt][1]), "r"(a[mt][2]), "r"(a[mt][3]),
                          "r"(bq[nt][0]), "r"(bq[nt][1]));
                }
        }
    }

    // ---- epilogue: bias + tanh + V-dot, reduce to per-row partials ----
    __syncthreads();
    const int t4 = lane & 3;
    float part[2][2];
#pragma unroll
    for (int mt = 0; mt < 2; mt++) { part[mt][0] = 0.f; part[mt][1] = 0.f; }
#pragma unroll
    for (int mt = 0; mt < 2; mt++)
#pragma unroll
        for (int nt = 0; nt < 8; nt++) {
            int n0 = wn * 64 + nt * 8 + 2 * t4;
            float v0 = Vs[n0], v1 = Vs[n0 + 1];
            float g0 = gBs[n0], g1 = gBs[n0 + 1];
            part[mt][0] += tanh_fast(acc[mt][nt][0] + g0) * v0 +
                           tanh_fast(acc[mt][nt][1] + g1) * v1;
            part[mt][1] += tanh_fast(acc[mt][nt][2] + g0) * v0 +
                           tanh_fast(acc[mt][nt][3] + g1) * v1;
        }
#pragma unroll
    for (int mt = 0; mt < 2; mt++)
#pragma unroll
        for (int rr = 0; rr < 2; rr++) {
            part[mt][rr] += __shfl_xor_sync(0xffffffffu, part[mt][rr], 1);
            part[mt][rr] += __shfl_xor_sync(0xffffffffu, part[mt][rr], 2);
        }
    if (t4 == 0) {
        int g = lane >> 2;
#pragma unroll
        for (int mt = 0; mt < 2; mt++)
#pragma unroll
            for (int rr = 0; rr < 2; rr++) {
                int row = wm * 32 + mt * 16 + rr * 8 + g;
                sPart[row * 4 + wn] = part[mt][rr];
            }
    }
    __syncthreads();
    if (tid < 128) {
        float s = sPart[tid * 4] + sPart[tid * 4 + 1] + sPart[tid * 4 + 2] +
                  sPart[tid * 4 + 3];
        atomicAdd(&g_scores[b * SS + s0 + tid], s);
    }
}

// ---------------------------------------------------------------------------
// kernC: softmax over S; writes attn; zeroes context region
// ---------------------------------------------------------------------------
__global__ __launch_bounds__(256) void kernC(float* __restrict__ out) {
    __shared__ float red[256];
    int b = blockIdx.x, tid = threadIdx.x;
    float v[8];
    float mx = -1e30f;
#pragma unroll
    for (int j = 0; j < 8; j++) {
        v[j] = g_scores[b * SS + tid + j * 256];
        mx = fmaxf(mx, v[j]);
    }
    red[tid] = mx;
    __syncthreads();
    for (int o = 128; o > 0; o >>= 1) {
        if (tid < o) red[tid] = fmaxf(red[tid], red[tid + o]);
        __syncthreads();
    }
    mx = red[0];
    __syncthreads();
    float s = 0.0f;
#pragma unroll
    for (int j = 0; j < 8; j++) {
        v[j] = __expf(v[j] - mx);
        s += v[j];
    }
    red[tid] = s;
    __syncthreads();
    for (int o = 128; o > 0; o >>= 1) {
        if (tid < o) red[tid] += red[tid + o];
        __syncthreads();
    }
    float inv = 1.0f / red[0];
#pragma unroll
    for (int j = 0; j < 8; j++)
        out[BB * UU + b * SS + tid + j * 256] = v[j] * inv;
    for (int i = tid; i < 512; i += 256) out[b * 512 + i] = 0.0f;
}

// ---------------------------------------------------------------------------
// kernD: context[b,d] = sum_s attn[b,s] * enc[b,s,d]
// ---------------------------------------------------------------------------
__global__ __launch_bounds__(512) void kernD(const float* __restrict__ enc,
                                             float* __restrict__ out) {
    __shared__ float as[128];
    int b = blockIdx.y, c = blockIdx.x, tid = threadIdx.x;
    if (tid < 128) as[tid] = out[BB * UU + b * SS + c * 128 + tid];
    __syncthreads();
    const float* e = enc + ((size_t)(b * SS + c * 128)) * DD + tid;
    float acc = 0.0f;
#pragma unroll 8
    for (int i = 0; i < 128; i++) acc = fmaf(as[i], e[(size_t)i * DD], acc);
    atomicAdd(&out[b * 512 + tid], acc);
}

// ---------------------------------------------------------------------------
extern "C" void kernel_launch(void* const* d_in, const int* in_sizes, int n_in,
                              void* d_out, int out_size) {
    const float* enc = (const float*)d_in[0];
    const float* dec = (const float*)d_in[1];
    const float* W1  = (const float*)d_in[2];
    const float* b1  = (const float*)d_in[3];
    const float* W2  = (const float*)d_in[4];
    const float* b2  = (const float*)d_in[5];
    const float* V   = (const float*)d_in[6];
    float* out = (float*)d_out;

    cudaFuncSetAttribute(kernB, cudaFuncAttributeMaxDynamicSharedMemorySize,
                         SMEM_B_TOTAL);

    kernE<<<65536, 256>>>(enc);
    kernW<<<1024, 256>>>(W1);
    kernA<<<BB, 512>>>(dec, W2, b1, b2);
    kernB<<<dim3(1024, 2), 512, SMEM_B_TOTAL>>>(V);
    kernC<<<BB, 256>>>(out);
    kernD<<<dim3(16, BB), 512>>>(enc, out);
}

// round 9
// speedup vs baseline: 1.3355x; 1.0584x over previous
#include <cuda_runtime.h>
#include <cuda_bf16.h>
#include <cstdint>

#define BB 64
#define SS 2048
#define DD 512
#define UU 512

// ---------------- scratch globals (no allocations allowed) ------------------
__device__ float g_bias[BB * UU];                  // dec@W2 + b1 + b2
__device__ float g_scores[BB * SS];                // pre-softmax scores
// enc converted: row r -> [hi k0..511 | lo k0..511] bf16  (256 MB)
__device__ __nv_bfloat16 g_encA[(size_t)BB * SS * 1024];
// W1 converted to [u][ hi k0..511 | lo k0..511 ]  (1 MB)
__device__ __nv_bfloat16 g_W1img[(size_t)UU * 1024];

// ---------------- helpers ----------------------------------------------------
__device__ __forceinline__ float tanh_fast(float x) {
    float e = __expf(2.0f * x);
    return 1.0f - __fdividef(2.0f, e + 1.0f);
}
__device__ __forceinline__ uint32_t smem_u32(const void* p) {
    uint32_t a;
    asm("{ .reg .u64 t; cvta.to.shared.u64 t, %1; cvt.u32.u64 %0, t; }"
        : "=r"(a) : "l"(p));
    return a;
}
__device__ __forceinline__ uint32_t pack2(__nv_bfloat16 a, __nv_bfloat16 b) {
    return ((uint32_t)__bfloat16_as_ushort(b) << 16) | __bfloat16_as_ushort(a);
}
#define CP16(dst, src) \
    asm volatile("cp.async.cg.shared.global [%0], [%1], 16;" \
                 :: "r"(dst), "l"(src) : "memory")

// ---------------------------------------------------------------------------
// kernE: enc fp32 -> bf16 hi/lo image
// ---------------------------------------------------------------------------
__global__ __launch_bounds__(256) void kernE(const float* __restrict__ enc) {
    size_t lin = (size_t)blockIdx.x * 256 + threadIdx.x;
    size_t row = lin >> 7;
    int q = (int)(lin & 127);
    float4 f = *(const float4*)(enc + row * DD + q * 4);
    __nv_bfloat16 h0 = __float2bfloat16_rn(f.x), h1 = __float2bfloat16_rn(f.y);
    __nv_bfloat16 h2 = __float2bfloat16_rn(f.z), h3 = __float2bfloat16_rn(f.w);
    __nv_bfloat16 l0 = __float2bfloat16_rn(f.x - __bfloat162float(h0));
    __nv_bfloat16 l1 = __float2bfloat16_rn(f.y - __bfloat162float(h1));
    __nv_bfloat16 l2 = __float2bfloat16_rn(f.z - __bfloat162float(h2));
    __nv_bfloat16 l3 = __float2bfloat16_rn(f.w - __bfloat162float(h3));
    uint2 hv = {pack2(h0, h1), pack2(h2, h3)};
    uint2 lv = {pack2(l0, l1), pack2(l2, l3)};
    *(uint2*)(&g_encA[row * 1024 + q * 4]) = hv;
    *(uint2*)(&g_encA[row * 1024 + 512 + q * 4]) = lv;
}

// ---------------------------------------------------------------------------
// kernW: W1[k][u] -> g_W1img[u][hi k | lo k]; also zero g_scores
// ---------------------------------------------------------------------------
__global__ __launch_bounds__(256) void kernW(const float* __restrict__ W1) {
    int idx = blockIdx.x * 256 + threadIdx.x;
    int u = idx & 511, kg = idx >> 9;
    float x = W1[(size_t)kg * UU + u];
    __nv_bfloat16 h = __float2bfloat16_rn(x);
    __nv_bfloat16 l = __float2bfloat16_rn(x - __bfloat162float(h));
    g_W1img[(size_t)u * 1024 + kg] = h;
    g_W1img[(size_t)u * 1024 + 512 + kg] = l;
    if (idx < BB * SS) g_scores[idx] = 0.0f;
}

// ---------------------------------------------------------------------------
// kernA: g_bias[b,u] = dec@W2 + b1 + b2
// ---------------------------------------------------------------------------
__global__ __launch_bounds__(512) void kernA(const float* __restrict__ dec,
                                             const float* __restrict__ W2,
                                             const float* __restrict__ b1,
                                             const float* __restrict__ b2) {
    __shared__ float ds[DD];
    int b = blockIdx.x;
    for (int i = threadIdx.x; i < DD; i += blockDim.x) ds[i] = dec[b * DD + i];
    __syncthreads();
    int u = threadIdx.x;
    float acc = 0.0f;
#pragma unroll 8
    for (int k = 0; k < DD; k++) acc = fmaf(ds[k], W2[k * UU + u], acc);
    g_bias[b * UU + u] = acc + b1[u] + b2[u];
}

// ---------------------------------------------------------------------------
// kernB: bf16 mma.sync GEMM, tile M64 x N256 per CTA, K'=1536 (3 passes).
// 256 threads (8 warps, warp tile 32x64), 2-stage cp.async ring,
// 2 CTAs/SM for independent barrier overlap.
// ---------------------------------------------------------------------------
#define ASLOT 9216              // 64 rows * 144 B
#define SLOT  46080             // A (9216) + B (36864) per stage
#define EXTRA 92160             // 2 stages
#define SMEM_B_TOTAL (EXTRA + 1024 + 1024 + 1024)

__global__ __launch_bounds__(256, 2) void kernB(const float* __restrict__ Vp) {
    extern __shared__ char smraw[];
    const uint32_t smem = smem_u32(smraw);
    float* gBs = (float*)(smraw + EXTRA);
    float* Vs = (float*)(smraw + EXTRA + 1024);
    float* sPart = (float*)(smraw + EXTRA + 2048);

    const int tid = threadIdx.x;
    const int lane = tid & 31, w = tid >> 5;
    const int wm = w & 1, wn = w >> 1;          // warp tile 32(M) x 64(N)
    const int R = blockIdx.x * 64;
    const int b = blockIdx.x >> 5;
    const int s0 = (blockIdx.x & 31) * 64;
    const int N0 = blockIdx.y * 256;

    {
        gBs[tid] = g_bias[b * 512 + N0 + tid];
        Vs[tid] = Vp[N0 + tid];
    }

    // tile it: pass p = it/8 (0: hi*hi, 1: hi*lo, 2: lo*hi), k0 = (it%8)*64
    auto issue_tile = [&](int it, int slot) {
        int p = it >> 3;
        int k0 = (it & 7) * 64;
        uint32_t aPart = (p < 2) ? 0u : 1024u;
        uint32_t bPart = (p == 1) ? 1024u : 0u;
        const char* aSrc = (const char*)g_encA + (size_t)R * 2048 + aPart + k0 * 2;
        const char* bSrc = (const char*)g_W1img + (size_t)N0 * 2048 + bPart + k0 * 2;
        uint32_t aDst = smem + slot * SLOT;
        uint32_t bDst = aDst + ASLOT;
        // A: 512 16B data chunks (64 rows x 8 chunks; 9th chunk/row is pad)
#pragma unroll
        for (int i = 0; i < 2; i++) {
            int lin = tid + i * 256;
            int row = lin >> 3, c = lin & 7;
            CP16(aDst + row * 144 + c * 16, aSrc + (size_t)row * 2048 + c * 16);
        }
        // B: 2048 chunks (256 rows x 8)
#pragma unroll
        for (int i = 0; i < 8; i++) {
            int lin = tid + i * 256;
            int row = lin >> 3, c = lin & 7;
            CP16(bDst + row * 144 + c * 16, bSrc + (size_t)row * 2048 + c * 16);
        }
        asm volatile("cp.async.commit_group;" ::: "memory");
    };

    float acc[2][8][4];
#pragma unroll
    for (int mt = 0; mt < 2; mt++)
#pragma unroll
        for (int nt = 0; nt < 8; nt++)
#pragma unroll
            for (int j = 0; j < 4; j++) acc[mt][nt][j] = 0.0f;

    issue_tile(0, 0);

    const uint32_t aRowOff =
        (uint32_t)((wm * 32 + (lane & 15)) * 144 + ((lane >> 4) & 1) * 16);
    // B x4 (two 8-row n-tiles per load): row = wn*64 + (lane&7) + bit4*8
    const uint32_t bRowOff =
        (uint32_t)((wn * 64 + (lane & 7) + ((lane >> 4) & 1) * 8) * 144 +
                   ((lane >> 3) & 1) * 16);

    for (int it = 0; it < 24; it++) {
        asm volatile("cp.async.wait_group 0;" ::: "memory");
        __syncthreads();
        // slot (it+1)&1 held tile it-1; all warps finished it-1 (sync above)
        if (it + 1 < 24) issue_tile(it + 1, (it + 1) & 1);

        const uint32_t sbase = smem + (it & 1) * SLOT;
        const uint32_t sA = sbase + aRowOff;
        const uint32_t sB = sbase + ASLOT + bRowOff;
#pragma unroll
        for (int ks = 0; ks < 4; ks++) {
            uint32_t a[2][4];
#pragma unroll
            for (int mt = 0; mt < 2; mt++) {
                asm volatile(
                    "ldmatrix.sync.aligned.m8n8.x4.shared.b16 {%0,%1,%2,%3}, [%4];"
                    : "=r"(a[mt][0]), "=r"(a[mt][1]), "=r"(a[mt][2]), "=r"(a[mt][3])
                    : "r"(sA + mt * 16 * 144 + ks * 32));
            }
            uint32_t bq[8][2];
#pragma unroll
            for (int ntp = 0; ntp < 4; ntp++) {
                asm volatile(
                    "ldmatrix.sync.aligned.m8n8.x4.shared.b16 {%0,%1,%2,%3}, [%4];"
                    : "=r"(bq[ntp * 2][0]), "=r"(bq[ntp * 2][1]),
                      "=r"(bq[ntp * 2 + 1][0]), "=r"(bq[ntp * 2 + 1][1])
                    : "r"(sB + ntp * 16 * 144 + ks * 32));
            }
#pragma unroll
            for (int mt = 0; mt < 2; mt++)
#pragma unroll
                for (int nt = 0; nt < 8; nt++) {
                    asm volatile(
                        "mma.sync.aligned.m16n8k16.row.col.f32.bf16.bf16.f32 "
                        "{%0,%1,%2,%3}, {%4,%5,%6,%7}, {%8,%9}, {%0,%1,%2,%3};"
                        : "+f"(acc[mt][nt][0]), "+f"(acc[mt][nt][1]),
                          "+f"(acc[mt][nt][2]), "+f"(acc[mt][nt][3])
                        : "r"(a[mt][0]), "r"(a[mt][1]), "r"(a[mt][2]), "r"(a[mt][3]),
                          "r"(bq[nt][0]), "r"(bq[nt][1]));
                }
        }
    }

    // ---- epilogue: bias + tanh + V-dot, reduce to per-row partials ----
    __syncthreads();
    const int t4 = lane & 3;
    float part[2][2];
#pragma unroll
    for (int mt = 0; mt < 2; mt++) { part[mt][0] = 0.f; part[mt][1] = 0.f; }
#pragma unroll
    for (int mt = 0; mt < 2; mt++)
#pragma unroll
        for (int nt = 0; nt < 8; nt++) {
            int n0 = wn * 64 + nt * 8 + 2 * t4;
            float v0 = Vs[n0], v1 = Vs[n0 + 1];
            float g0 = gBs[n0], g1 = gBs[n0 + 1];
            part[mt][0] += tanh_fast(acc[mt][nt][0] + g0) * v0 +
                           tanh_fast(acc[mt][nt][1] + g1) * v1;
            part[mt][1] += tanh_fast(acc[mt][nt][2] + g0) * v0 +
                           tanh_fast(acc[mt][nt][3] + g1) * v1;
        }
#pragma unroll
    for (int mt = 0; mt < 2; mt++)
#pragma unroll
        for (int rr = 0; rr < 2; rr++) {
            part[mt][rr] += __shfl_xor_sync(0xffffffffu, part[mt][rr], 1);
            part[mt][rr] += __shfl_xor_sync(0xffffffffu, part[mt][rr], 2);
        }
    if (t4 == 0) {
        int g = lane >> 2;
#pragma unroll
        for (int mt = 0; mt < 2; mt++)
#pragma unroll
            for (int rr = 0; rr < 2; rr++) {
                int row = wm * 32 + mt * 16 + rr * 8 + g;
                sPart[row * 4 + wn] = part[mt][rr];
            }
    }
    __syncthreads();
    if (tid < 64) {
        float s = sPart[tid * 4] + sPart[tid * 4 + 1] + sPart[tid * 4 + 2] +
                  sPart[tid * 4 + 3];
        atomicAdd(&g_scores[b * SS + s0 + tid], s);
    }
}

// ---------------------------------------------------------------------------
// kernC: softmax over S; writes attn; zeroes context region
// ---------------------------------------------------------------------------
__global__ __launch_bounds__(256) void kernC(float* __restrict__ out) {
    __shared__ float red[256];
    int b = blockIdx.x, tid = threadIdx.x;
    float v[8];
    float mx = -1e30f;
#pragma unroll
    for (int j = 0; j < 8; j++) {
        v[j] = g_scores[b * SS + tid + j * 256];
        mx = fmaxf(mx, v[j]);
    }
    red[tid] = mx;
    __syncthreads();
    for (int o = 128; o > 0; o >>= 1) {
        if (tid < o) red[tid] = fmaxf(red[tid], red[tid + o]);
        __syncthreads();
    }
    mx = red[0];
    __syncthreads();
    float s = 0.0f;
#pragma unroll
    for (int j = 0; j < 8; j++) {
        v[j] = __expf(v[j] - mx);
        s += v[j];
    }
    red[tid] = s;
    __syncthreads();
    for (int o = 128; o > 0; o >>= 1) {
        if (tid < o) red[tid] += red[tid + o];
        __syncthreads();
    }
    float inv = 1.0f / red[0];
#pragma unroll
    for (int j = 0; j < 8; j++)
        out[BB * UU + b * SS + tid + j * 256] = v[j] * inv;
    for (int i = tid; i < 512; i += 256) out[b * 512 + i] = 0.0f;
}

// ---------------------------------------------------------------------------
// kernD: context[b,d] = sum_s attn[b,s] * enc[b,s,d]
// ---------------------------------------------------------------------------
__global__ __launch_bounds__(512) void kernD(const float* __restrict__ enc,
                                             float* __restrict__ out) {
    __shared__ float as[128];
    int b = blockIdx.y, c = blockIdx.x, tid = threadIdx.x;
    if (tid < 128) as[tid] = out[BB * UU + b * SS + c * 128 + tid];
    __syncthreads();
    const float* e = enc + ((size_t)(b * SS + c * 128)) * DD + tid;
    float acc = 0.0f;
#pragma unroll 8
    for (int i = 0; i < 128; i++) acc = fmaf(as[i], e[(size_t)i * DD], acc);
    atomicAdd(&out[b * 512 + tid], acc);
}

// ---------------------------------------------------------------------------
extern "C" void kernel_launch(void* const* d_in, const int* in_sizes, int n_in,
                              void* d_out, int out_size) {
    const float* enc = (const float*)d_in[0];
    const float* dec = (const float*)d_in[1];
    const float* W1  = (const float*)d_in[2];
    const float* b1  = (const float*)d_in[3];
    const float* W2  = (const float*)d_in[4];
    const float* b2  = (const float*)d_in[5];
    const float* V   = (const float*)d_in[6];
    float* out = (float*)d_out;

    cudaFuncSetAttribute(kernB, cudaFuncAttributeMaxDynamicSharedMemorySize,
                         SMEM_B_TOTAL);

    kernE<<<65536, 256>>>(enc);
    kernW<<<1024, 256>>>(W1);
    kernA<<<BB, 512>>>(dec, W2, b1, b2);
    kernB<<<dim3(2048, 2), 256, SMEM_B_TOTAL>>>(V);
    kernC<<<BB, 256>>>(out);
    kernD<<<dim3(16, BB), 512>>>(enc, out);
}